// round 2
// baseline (speedup 1.0000x reference)
#include <cuda_runtime.h>
#include <cuda_bf16.h>

#define NUM_NODES 10000
#define N_EDGES   640000
#define D         128

// ---------------- device scratch ----------------
__device__ float d_S[NUM_NODES * D];
__device__ float d_A[NUM_NODES * D];
__device__ int   d_deg[NUM_NODES];
__device__ int   d_off[NUM_NODES + 1];
__device__ int   d_cur[NUM_NODES];
__device__ float d_degf[NUM_NODES];
__device__ int2  d_perm2[N_EDGES];          // (edge id, src node)
__device__ float d_Mf[512 * D];
__device__ float d_cvec[D];
__device__ int   d_is64;

// ---------------- helpers ----------------
__device__ __forceinline__ int load_idx(const void* ei, int which, int e, int is64) {
    if (is64) {
        const long long* p = (const long long*)ei;
        return (int)__ldg(p + (size_t)which * N_EDGES + e);
    } else {
        const int* p = (const int*)ei;
        return __ldg(p + (size_t)which * N_EDGES + e);
    }
}
__device__ __forceinline__ float4 ldg4(const float* p)  { return __ldg((const float4*)p); }
__device__ __forceinline__ float4 ldcs4(const float* p) { return __ldcs((const float4*)p); }

__device__ __forceinline__ unsigned long long pack2(float v) {
    unsigned long long r;
    asm("mov.b64 %0, {%1, %1};" : "=l"(r) : "f"(v));
    return r;
}
#define FMA_F32X2(d, a, b) asm("fma.rn.f32x2 %0, %1, %2, %0;" : "+l"(d) : "l"(a), "l"(b))

// ---------------- K0: dtype probe + zero d_deg ----------------
__global__ void k_init(const int* ei_words) {
    int t = threadIdx.x;
    if (blockIdx.x == 0) {
        // probe high words of first 256 entries; int64 indices < 10000 -> all zero
        int w = ei_words[2 * t + 1];
        int any = __syncthreads_or(w != 0);
        if (t == 0) d_is64 = (any == 0) ? 1 : 0;
    } else {
        int i = (blockIdx.x - 1) * 256 + t;
        if (i < NUM_NODES) d_deg[i] = 0;
    }
}

// ---------------- K1: fuse weights ----------------
// Mf rows: [0,128)=W1a@W2a  [128,256)=W1c@W2a  [256,384)=W2b  [384,512)=W1b@W2a
__global__ void k_fuse(const float* __restrict__ W1,
                       const float* __restrict__ b1,
                       const float* __restrict__ W2) {
    __shared__ float row[D];
    int r = blockIdx.x, o = threadIdx.x;
    if (r >= 256 && r < 384) {
        d_Mf[r * D + o] = W2[(128 + (r - 256)) * D + o];
        return;
    }
    int w1row = (r < 128) ? r : (r < 256) ? (256 + (r - 128)) : (128 + (r - 384));
    row[o] = W1[w1row * D + o];
    __syncthreads();
    float acc = 0.f;
#pragma unroll 8
    for (int h = 0; h < D; h++) acc += row[h] * __ldg(W2 + h * D + o);
    d_Mf[r * D + o] = acc;
    if (r == 0) {
        __syncthreads();
        row[o] = b1[o];
        __syncthreads();
        float c = 0.f;
#pragma unroll 8
        for (int h = 0; h < D; h++) c += row[h] * __ldg(W2 + h * D + o);
        d_cvec[o] = c;
    }
}

// ---------------- K2: degree count ----------------
__global__ void k_deg(const void* ei) {
    int is64 = d_is64;
    int e = blockIdx.x * blockDim.x + threadIdx.x;
    if (e >= N_EDGES) return;
    int dst = load_idx(ei, 1, e, is64);
    atomicAdd(&d_deg[dst], 1);
}

// ---------------- K3: exclusive scan ----------------
__global__ void k_scan() {
    __shared__ int s[1024];
    int t = threadIdx.x;
    int base = t * 10;
    int degs[10];
    int loc = 0;
#pragma unroll
    for (int i = 0; i < 10; i++) {
        int n = base + i;
        degs[i] = (n < NUM_NODES) ? d_deg[n] : 0;
        loc += degs[i];
    }
    s[t] = loc;
    __syncthreads();
    for (int d = 1; d < 1024; d <<= 1) {
        int v = (t >= d) ? s[t - d] : 0;
        __syncthreads();
        s[t] += v;
        __syncthreads();
    }
    int run = s[t] - loc;
#pragma unroll
    for (int i = 0; i < 10; i++) {
        int n = base + i;
        if (n < NUM_NODES) {
            d_off[n]  = run;
            d_cur[n]  = run;
            d_degf[n] = (float)degs[i];
            run += degs[i];
        }
    }
    if (t == 1023) d_off[NUM_NODES] = s[1023];
}

// ---------------- K4: scatter (edge, src) into CSR buckets ----------------
__global__ void k_scatter(const void* ei) {
    int is64 = d_is64;
    int e = blockIdx.x * blockDim.x + threadIdx.x;
    if (e >= N_EDGES) return;
    int dst = load_idx(ei, 1, e, is64);
    int src = load_idx(ei, 0, e, is64);
    int pos = atomicAdd(&d_cur[dst], 1);
    d_perm2[pos] = make_int2(e, src);
}

// ---------------- K5: atomic-free segment sums (warp per node) ----------------
__global__ void __launch_bounds__(256, 2)
k_agg(const float* __restrict__ x, const float* __restrict__ ea) {
    int n = blockIdx.x * 8 + (threadIdx.x >> 5);
    if (n >= NUM_NODES) return;
    int lane = threadIdx.x & 31;
    int j0 = d_off[n], j1 = d_off[n + 1];

    float4 aS = make_float4(0.f, 0.f, 0.f, 0.f);
    float4 aA = make_float4(0.f, 0.f, 0.f, 0.f);

    int j = j0;
    for (; j + 8 <= j1; j += 8) {
        int2 p[8];
#pragma unroll
        for (int v = 0; v < 8; v++) p[v] = __ldg(d_perm2 + j + v);
        float4 xv[8], av[8];
#pragma unroll
        for (int v = 0; v < 8; v++) xv[v] = ldg4(x + (size_t)p[v].y * D + lane * 4);
#pragma unroll
        for (int v = 0; v < 8; v++) av[v] = ldcs4(ea + (size_t)p[v].x * D + lane * 4);
#pragma unroll
        for (int v = 0; v < 8; v++) {
            aS.x += xv[v].x; aS.y += xv[v].y; aS.z += xv[v].z; aS.w += xv[v].w;
            aA.x += av[v].x; aA.y += av[v].y; aA.z += av[v].z; aA.w += av[v].w;
        }
    }
    for (; j < j1; j++) {
        int2 p = __ldg(d_perm2 + j);
        float4 xv = ldg4(x + (size_t)p.y * D + lane * 4);
        float4 av = ldcs4(ea + (size_t)p.x * D + lane * 4);
        aS.x += xv.x; aS.y += xv.y; aS.z += xv.z; aS.w += xv.w;
        aA.x += av.x; aA.y += av.y; aA.z += av.z; aA.w += av.w;
    }
    *(float4*)(d_S + (size_t)n * D + lane * 4) = aS;
    *(float4*)(d_A + (size_t)n * D + lane * 4) = aA;
}

// ---------------- K6: fused node GEMM with packed f32x2 FMA ----------------
// out[10000,128] = [S | A | x | deg*x] @ Mf + deg (x) cvec + b2
// Tile: 32 nodes x 128 outs, 256 threads, thread = 2 nodes x 8 outs (4 f32x2 pairs)
__global__ void __launch_bounds__(256)
k_gemm(const float* __restrict__ x,
       const float* __restrict__ b2,
       float* __restrict__ out) {
    __shared__ float Us[32 * 33];
    __shared__ float Ms[32 * 128];
    int t = threadIdx.x;
    int n0 = blockIdx.x * 32;
    int og = t & 15;          // 16 groups of 8 outputs
    int ng = t >> 4;          // 16 groups of 2 nodes

    unsigned long long acc[2][4];
#pragma unroll
    for (int i = 0; i < 2; i++)
#pragma unroll
        for (int j = 0; j < 4; j++) acc[i][j] = 0ull;

    for (int k0 = 0; k0 < 512; k0 += 32) {
        int region = k0 >> 7;
        int kloc = k0 & 127;
        const float* base = (region == 0) ? d_S : (region == 1) ? d_A : x;

        // U tile: 32x32 floats, 1 float4 per thread
        {
            int r = t >> 3, c = (t & 7) * 4;
            int n = n0 + r;
            float4 val = make_float4(0.f, 0.f, 0.f, 0.f);
            if (n < NUM_NODES) {
                val = ldg4(base + (size_t)n * D + kloc + c);
                if (region == 3) {
                    float dg = d_degf[n];
                    val.x *= dg; val.y *= dg; val.z *= dg; val.w *= dg;
                }
            }
            Us[r * 33 + c + 0] = val.x;
            Us[r * 33 + c + 1] = val.y;
            Us[r * 33 + c + 2] = val.z;
            Us[r * 33 + c + 3] = val.w;
        }
        // M tile: 32x128 floats, 4 float4 per thread
#pragma unroll
        for (int v = 0; v < 4; v++) {
            int id = t * 16 + v * 4;
            int r = id >> 7, c = id & 127;
            *(float4*)(Ms + r * 128 + c) = ldg4(d_Mf + (size_t)(k0 + r) * 128 + c);
        }
        __syncthreads();

#pragma unroll
        for (int kk = 0; kk < 32; kk++) {
            unsigned long long u0 = pack2(Us[(ng * 2 + 0) * 33 + kk]);
            unsigned long long u1 = pack2(Us[(ng * 2 + 1) * 33 + kk]);
            const unsigned long long* mrow =
                (const unsigned long long*)(Ms + kk * 128 + og * 8);
#pragma unroll
            for (int j = 0; j < 4; j++) {
                unsigned long long m = mrow[j];
                FMA_F32X2(acc[0][j], u0, m);
                FMA_F32X2(acc[1][j], u1, m);
            }
        }
        __syncthreads();
    }

    // epilogue: + deg*cvec + b2
#pragma unroll
    for (int i = 0; i < 2; i++) {
        int n = n0 + ng * 2 + i;
        if (n >= NUM_NODES) continue;
        float dg = d_degf[n];
        float o8[8];
#pragma unroll
        for (int j = 0; j < 4; j++) {
            float lo, hi;
            asm("mov.b64 {%0, %1}, %2;" : "=f"(lo), "=f"(hi) : "l"(acc[i][j]));
            int o = og * 8 + 2 * j;
            o8[2 * j + 0] = lo + dg * d_cvec[o + 0] + b2[o + 0];
            o8[2 * j + 1] = hi + dg * d_cvec[o + 1] + b2[o + 1];
        }
        float4* outp = (float4*)(out + (size_t)n * D + og * 8);
        outp[0] = make_float4(o8[0], o8[1], o8[2], o8[3]);
        outp[1] = make_float4(o8[4], o8[5], o8[6], o8[7]);
    }
}

// ---------------- launch ----------------
extern "C" void kernel_launch(void* const* d_in, const int* in_sizes, int n_in,
                              void* d_out, int out_size) {
    const float* x  = (const float*)d_in[0];
    const void*  ei = d_in[1];
    const float* ea = (const float*)d_in[2];
    const float* W1 = (const float*)d_in[3];
    const float* b1 = (const float*)d_in[4];
    const float* W2 = (const float*)d_in[5];
    const float* b2 = (const float*)d_in[6];
    float* out = (float*)d_out;

    k_init<<<41, 256>>>((const int*)ei);
    k_fuse<<<512, 128>>>(W1, b1, W2);
    k_deg<<<(N_EDGES + 255) / 256, 256>>>(ei);
    k_scan<<<1, 1024>>>();
    k_scatter<<<(N_EDGES + 255) / 256, 256>>>(ei);
    k_agg<<<(NUM_NODES + 7) / 8, 256>>>(x, ea);
    k_gemm<<<(NUM_NODES + 31) / 32, 256>>>(x, b2, out);
}

// round 3
// speedup vs baseline: 1.3180x; 1.3180x over previous
#include <cuda_runtime.h>
#include <cuda_bf16.h>

#define NUM_NODES 10000
#define N_EDGES   640000
#define D         128
#define BUCKET    128          // slots per node; overflow handled exactly
#define OVF_MAX   4096

// ---------------- device scratch ----------------
__device__ float d_S[NUM_NODES * D];
__device__ float d_A[NUM_NODES * D];
__device__ int   d_cur[NUM_NODES];          // atomic counters -> final degrees
__device__ float d_degf[NUM_NODES];
__device__ int2  d_perm2[NUM_NODES * BUCKET]; // (edge id, src) per dst bucket
__device__ int3  d_ovf[OVF_MAX];
__device__ int   d_ovf_cnt;
__device__ float d_Mf[512 * D];
__device__ float d_cvec[D];
__device__ int   d_is64;

// ---------------- helpers ----------------
__device__ __forceinline__ int load_idx(const void* ei, int which, int e, int is64) {
    if (is64) {
        const long long* p = (const long long*)ei;
        return (int)__ldg(p + (size_t)which * N_EDGES + e);
    } else {
        const int* p = (const int*)ei;
        return __ldg(p + (size_t)which * N_EDGES + e);
    }
}
__device__ __forceinline__ float4 ldg4(const float* p)  { return __ldg((const float4*)p); }
__device__ __forceinline__ float4 ldcs4(const float* p) { return __ldcs((const float4*)p); }

// ---------------- K0: dtype probe + zero counters ----------------
__global__ void k_init(const int* ei_words) {
    int t = threadIdx.x;
    if (blockIdx.x == 0) {
        int w = ei_words[2 * t + 1];            // high words if int64
        int any = __syncthreads_or(w != 0);
        if (t == 0) { d_is64 = (any == 0) ? 1 : 0; d_ovf_cnt = 0; }
    } else {
        int i = (blockIdx.x - 1) * 256 + t;
        if (i < NUM_NODES) d_cur[i] = 0;
    }
}

// ---------------- K1: fuse weights ----------------
// Mf rows: [0,128)=W1a@W2a  [128,256)=W1c@W2a  [256,384)=W2b  [384,512)=W1b@W2a
__global__ void k_fuse(const float* __restrict__ W1,
                       const float* __restrict__ b1,
                       const float* __restrict__ W2) {
    __shared__ float row[D];
    int r = blockIdx.x, o = threadIdx.x;
    if (r >= 256 && r < 384) {
        d_Mf[r * D + o] = W2[(128 + (r - 256)) * D + o];
        return;
    }
    int w1row = (r < 128) ? r : (r < 256) ? (256 + (r - 128)) : (128 + (r - 384));
    row[o] = W1[w1row * D + o];
    __syncthreads();
    float acc = 0.f;
#pragma unroll 8
    for (int h = 0; h < D; h++) acc += row[h] * __ldg(W2 + h * D + o);
    d_Mf[r * D + o] = acc;
    if (r == 0) {
        __syncthreads();
        row[o] = b1[o];
        __syncthreads();
        float c = 0.f;
#pragma unroll 8
        for (int h = 0; h < D; h++) c += row[h] * __ldg(W2 + h * D + o);
        d_cvec[o] = c;
    }
}

// ---------------- K2: single-pass bucket scatter (replaces deg+scan+scatter) ----------------
__global__ void k_scatter(const void* ei) {
    int is64 = d_is64;
    int e = blockIdx.x * blockDim.x + threadIdx.x;
    if (e >= N_EDGES) return;
    int dst = load_idx(ei, 1, e, is64);
    int src = load_idx(ei, 0, e, is64);
    int pos = atomicAdd(&d_cur[dst], 1);
    if (pos < BUCKET) {
        d_perm2[(dst << 7) + pos] = make_int2(e, src);
    } else {
        int o = atomicAdd(&d_ovf_cnt, 1);
        if (o < OVF_MAX) d_ovf[o] = make_int3(dst, e, src);
    }
}

// ---------------- K3: atomic-free segment sums (warp per node) ----------------
__global__ void k_agg(const float* __restrict__ x, const float* __restrict__ ea) {
    int n = blockIdx.x * 8 + (threadIdx.x >> 5);
    if (n >= NUM_NODES) return;
    int lane = threadIdx.x & 31;
    int deg = d_cur[n];
    if (lane == 0) d_degf[n] = (float)deg;
    int cnt = min(deg, BUCKET);
    const int2* bucket = d_perm2 + ((size_t)n << 7);

    float4 aS = make_float4(0.f, 0.f, 0.f, 0.f);
    float4 aA = make_float4(0.f, 0.f, 0.f, 0.f);

    int j = 0;
    for (; j + 4 <= cnt; j += 4) {
        int2 p0 = __ldg(bucket + j + 0);
        int2 p1 = __ldg(bucket + j + 1);
        int2 p2 = __ldg(bucket + j + 2);
        int2 p3 = __ldg(bucket + j + 3);
        float4 x0 = ldg4(x + (size_t)p0.y * D + lane * 4);
        float4 x1 = ldg4(x + (size_t)p1.y * D + lane * 4);
        float4 x2 = ldg4(x + (size_t)p2.y * D + lane * 4);
        float4 x3 = ldg4(x + (size_t)p3.y * D + lane * 4);
        float4 a0 = ldcs4(ea + (size_t)p0.x * D + lane * 4);
        float4 a1 = ldcs4(ea + (size_t)p1.x * D + lane * 4);
        float4 a2 = ldcs4(ea + (size_t)p2.x * D + lane * 4);
        float4 a3 = ldcs4(ea + (size_t)p3.x * D + lane * 4);
        aS.x += (x0.x + x1.x) + (x2.x + x3.x);
        aS.y += (x0.y + x1.y) + (x2.y + x3.y);
        aS.z += (x0.z + x1.z) + (x2.z + x3.z);
        aS.w += (x0.w + x1.w) + (x2.w + x3.w);
        aA.x += (a0.x + a1.x) + (a2.x + a3.x);
        aA.y += (a0.y + a1.y) + (a2.y + a3.y);
        aA.z += (a0.z + a1.z) + (a2.z + a3.z);
        aA.w += (a0.w + a1.w) + (a2.w + a3.w);
    }
    for (; j < cnt; j++) {
        int2 p = __ldg(bucket + j);
        float4 xv = ldg4(x + (size_t)p.y * D + lane * 4);
        float4 av = ldcs4(ea + (size_t)p.x * D + lane * 4);
        aS.x += xv.x; aS.y += xv.y; aS.z += xv.z; aS.w += xv.w;
        aA.x += av.x; aA.y += av.y; aA.z += av.z; aA.w += av.w;
    }
    *(float4*)(d_S + (size_t)n * D + lane * 4) = aS;
    *(float4*)(d_A + (size_t)n * D + lane * 4) = aA;
}

// ---------------- K4: exact fixup for bucket overflow (normally 0 entries) ----------------
__global__ void k_ovf(const float* __restrict__ x, const float* __restrict__ ea) {
    int cnt = d_ovf_cnt;
    if (cnt > OVF_MAX) cnt = OVF_MAX;
    int lane = threadIdx.x;   // 128
    for (int i = blockIdx.x; i < cnt; i += gridDim.x) {
        int3 v = d_ovf[i];    // (dst, e, src)
        atomicAdd(&d_S[(size_t)v.x * D + lane], __ldg(x  + (size_t)v.z * D + lane));
        atomicAdd(&d_A[(size_t)v.x * D + lane], __ldg(ea + (size_t)v.y * D + lane));
    }
}

// ---------------- K5: fused node GEMM (R1 known-good shape) ----------------
// out = [S | A | x | deg*x] @ Mf + deg (x) cvec + b2
// 64 nodes x 128 outs per block, 256 threads, 4x8 per thread, kc=32
__global__ void k_gemm(const float* __restrict__ x,
                       const float* __restrict__ b2,
                       float* __restrict__ out) {
    __shared__ float Us[64 * 33];
    __shared__ float Ms[32 * 128];
    int t = threadIdx.x;
    int n0 = blockIdx.x * 64;
    int og = t & 15;
    int ng = t >> 4;

    float acc[4][8];
#pragma unroll
    for (int i = 0; i < 4; i++)
#pragma unroll
        for (int jj = 0; jj < 8; jj++) acc[i][jj] = 0.f;

    for (int k0 = 0; k0 < 512; k0 += 32) {
        int region = k0 >> 7;
        int kloc = k0 & 127;
        const float* base = (region == 0) ? d_S : (region == 1) ? d_A : x;

#pragma unroll
        for (int v = 0; v < 2; v++) {
            int id = t * 8 + v * 4;
            int r = id >> 5, c = id & 31;
            int n = n0 + r;
            float4 val = make_float4(0.f, 0.f, 0.f, 0.f);
            if (n < NUM_NODES) {
                val = ldg4(base + (size_t)n * D + kloc + c);
                if (region == 3) {
                    float dg = d_degf[n];
                    val.x *= dg; val.y *= dg; val.z *= dg; val.w *= dg;
                }
            }
            Us[r * 33 + c + 0] = val.x;
            Us[r * 33 + c + 1] = val.y;
            Us[r * 33 + c + 2] = val.z;
            Us[r * 33 + c + 3] = val.w;
        }
#pragma unroll
        for (int v = 0; v < 4; v++) {
            int id = t * 16 + v * 4;
            int r = id >> 7, c = id & 127;
            *(float4*)(Ms + r * 128 + c) = ldg4(d_Mf + (size_t)(k0 + r) * 128 + c);
        }
        __syncthreads();

#pragma unroll
        for (int kk = 0; kk < 32; kk++) {
            float u[4];
#pragma unroll
            for (int i = 0; i < 4; i++) u[i] = Us[(ng * 4 + i) * 33 + kk];
            float4 m0 = *(float4*)(Ms + kk * 128 + og * 8);
            float4 m1 = *(float4*)(Ms + kk * 128 + og * 8 + 4);
            float m[8] = {m0.x, m0.y, m0.z, m0.w, m1.x, m1.y, m1.z, m1.w};
#pragma unroll
            for (int i = 0; i < 4; i++)
#pragma unroll
                for (int jj = 0; jj < 8; jj++)
                    acc[i][jj] += u[i] * m[jj];
        }
        __syncthreads();
    }

#pragma unroll
    for (int i = 0; i < 4; i++) {
        int n = n0 + ng * 4 + i;
        if (n >= NUM_NODES) continue;
        float dg = d_degf[n];
        float o8[8];
#pragma unroll
        for (int jj = 0; jj < 8; jj++) {
            int o = og * 8 + jj;
            o8[jj] = acc[i][jj] + dg * d_cvec[o] + b2[o];
        }
        float4* outp = (float4*)(out + (size_t)n * D + og * 8);
        outp[0] = make_float4(o8[0], o8[1], o8[2], o8[3]);
        outp[1] = make_float4(o8[4], o8[5], o8[6], o8[7]);
    }
}

// ---------------- launch ----------------
extern "C" void kernel_launch(void* const* d_in, const int* in_sizes, int n_in,
                              void* d_out, int out_size) {
    const float* x  = (const float*)d_in[0];
    const void*  ei = d_in[1];
    const float* ea = (const float*)d_in[2];
    const float* W1 = (const float*)d_in[3];
    const float* b1 = (const float*)d_in[4];
    const float* W2 = (const float*)d_in[5];
    const float* b2 = (const float*)d_in[6];
    float* out = (float*)d_out;

    k_init<<<41, 256>>>((const int*)ei);
    k_fuse<<<512, 128>>>(W1, b1, W2);
    k_scatter<<<(N_EDGES + 255) / 256, 256>>>(ei);
    k_agg<<<(NUM_NODES + 7) / 8, 256>>>(x, ea);       // profiled launch (index 3)
    k_ovf<<<4, 128>>>(x, ea);
    k_gemm<<<(NUM_NODES + 63) / 64, 256>>>(x, b2, out);
}